// round 2
// baseline (speedup 1.0000x reference)
#include <cuda_runtime.h>
#include <math.h>

#define BB 4
#define NN 197
#define DD 768
#define HH 12
#define HDIM 64
#define NHEAD (BB*HH)   /* 48 */

// Scratch (no allocations allowed): ~22 MB total
__device__ float g_q[NHEAD*NN*HDIM];
__device__ float g_k[NHEAD*NN*HDIM];
__device__ float g_v[NHEAD*NN*HDIM];
__device__ float g_P[NHEAD*NN*NN];

// ---------------------------------------------------------------------------
// K1: QKV projection. C = hidden(788x768) @ W(768x768) + bias, scattered into
// per-head layout g_{q,k,v}[(b*12+h)*197 + n][hd]. Classic 64x64x16 tile GEMM.
// grid (13, 36): blockIdx.y selects {Wq,Wk,Wv} x head-column-tile.
// ---------------------------------------------------------------------------
__global__ void __launch_bounds__(256) qkv_gemm(
    const float* __restrict__ hid,
    const float* __restrict__ Wq, const float* __restrict__ bq,
    const float* __restrict__ Wk, const float* __restrict__ bk,
    const float* __restrict__ Wv, const float* __restrict__ bv)
{
    __shared__ float As[16][64];   // transposed A tile
    __shared__ float Bs[16][64];
    const int tid   = threadIdx.x;
    const int tileM = blockIdx.x;          // 0..12
    const int tileN = blockIdx.y;          // 0..35
    const int w     = tileN / 12;          // which projection
    const int h     = tileN % 12;          // head (each 64-col tile == one head)
    const int nb    = h * 64;

    const float* W; const float* bias; float* outp;
    if (w == 0)      { W = Wq; bias = bq; outp = g_q; }
    else if (w == 1) { W = Wk; bias = bk; outp = g_k; }
    else             { W = Wv; bias = bv; outp = g_v; }

    const int m0 = tileM * 64;
    const int ty = tid >> 4, tx = tid & 15;
    float acc[4][4] = {};

    for (int k0 = 0; k0 < 768; k0 += 16) {
        // A tile 64x16 -> As[k][m] (transposed)
        {
            int r  = tid >> 2;
            int kk = (tid & 3) * 4;
            int gm = m0 + r;
            float4 a = make_float4(0.f, 0.f, 0.f, 0.f);
            if (gm < 788) a = *(const float4*)(hid + gm * 768 + k0 + kk);
            As[kk + 0][r] = a.x; As[kk + 1][r] = a.y;
            As[kk + 2][r] = a.z; As[kk + 3][r] = a.w;
        }
        // B tile 16x64
        {
            int kr = tid >> 4;
            int c  = (tid & 15) * 4;
            *(float4*)&Bs[kr][c] = *(const float4*)(W + (k0 + kr) * 768 + nb + c);
        }
        __syncthreads();
        #pragma unroll
        for (int kk = 0; kk < 16; kk++) {
            float4 av = *(float4*)&As[kk][ty * 4];
            float4 bv4 = *(float4*)&Bs[kk][tx * 4];
            float a4[4] = {av.x, av.y, av.z, av.w};
            float b4[4] = {bv4.x, bv4.y, bv4.z, bv4.w};
            #pragma unroll
            for (int i = 0; i < 4; i++)
                #pragma unroll
                for (int j = 0; j < 4; j++)
                    acc[i][j] = fmaf(a4[i], b4[j], acc[i][j]);
        }
        __syncthreads();
    }

    float4 bb = *(const float4*)(bias + nb + tx * 4);
    #pragma unroll
    for (int i = 0; i < 4; i++) {
        int m = m0 + ty * 4 + i;
        if (m < 788) {
            int b = m / 197, n = m % 197;
            float4 o;
            o.x = acc[i][0] + bb.x; o.y = acc[i][1] + bb.y;
            o.z = acc[i][2] + bb.z; o.w = acc[i][3] + bb.w;
            *(float4*)(outp + ((b * 12 + h) * 197 + n) * 64 + tx * 4) = o;
        }
    }
}

// ---------------------------------------------------------------------------
// K2: fused logits + 3-way softmax -> combined probability matrix P.
//   s12[i][j] = q_i . k_j            (softmax over j; also /8 variant)
//   s3 [i][j] = sum_d Ws[d]*tanh(k_i[d] + q_j[d])   (softmax over j)
//   P[i][j] = (softmax(s12) + softmax(s12/8) + softmax(s3))/3
// Thread = column j (q_j, k_j live in 128 registers). q_i/k_i broadcast from
// smem as packed float2. R=4 rows per pass. grid (3 chunks, 48 heads), 224 thr.
// ---------------------------------------------------------------------------
__device__ __forceinline__ float tanh_approx(float x) {
    float y; asm("tanh.approx.f32 %0, %1;" : "=f"(y) : "f"(x)); return y;
}
__device__ __forceinline__ float rcp_approx(float x) {
    float y; asm("rcp.approx.f32 %0, %1;" : "=f"(y) : "f"(x)); return y;
}

__global__ void __launch_bounds__(224) attn_probs_kernel(const float* __restrict__ Wsp)
{
    extern __shared__ float sm[];
    float2* qk  = (float2*)sm;            // [197][64]  (q, k) interleaved
    float*  wss = sm + 197 * 64 * 2;      // [64]
    __shared__ float red[7][20];

    const int head      = blockIdx.y;
    const int chunk     = blockIdx.x;
    const int row_begin = chunk * 66;
    const int row_end   = min(197, row_begin + 66);
    const int tid  = threadIdx.x;
    const int wid  = tid >> 5, lane = tid & 31;

    const float* qg = g_q + head * (197 * 64);
    const float* kg = g_k + head * (197 * 64);
    for (int idx = tid; idx < 197 * 64; idx += 224)
        qk[idx] = make_float2(qg[idx], kg[idx]);
    if (tid < 64) wss[tid] = Wsp[tid];
    __syncthreads();

    const bool active = (tid < 197);
    const int jj = active ? tid : 0;
    float qj[64], kj[64];
    #pragma unroll
    for (int d = 0; d < 64; d++) { float2 t = qk[jj * 64 + d]; qj[d] = t.x; kj[d] = t.y; }

    float* Prow = g_P + head * (197 * 197);

    for (int i0 = row_begin; i0 < row_end; i0 += 4) {
        const float2* qp[4];
        #pragma unroll
        for (int r = 0; r < 4; r++) qp[r] = qk + min(i0 + r, 196) * 64;

        float s12[4] = {0,0,0,0}, s3[4] = {0,0,0,0};
        #pragma unroll
        for (int d = 0; d < 64; d++) {
            float wsd = wss[d];
            float2 av[4];
            #pragma unroll
            for (int r = 0; r < 4; r++) av[r] = qp[r][d];   // broadcast LDS.64
            #pragma unroll
            for (int r = 0; r < 4; r++) {
                s12[r] = fmaf(av[r].x, kj[d], s12[r]);                  // q_i . k_j
                s3[r]  = fmaf(wsd, tanh_approx(av[r].y + qj[d]), s3[r]); // Ws.tanh(k_i+q_j)
            }
        }

        // ---- block max reduce (8 values) ----
        float m12[4], m3[4];
        #pragma unroll
        for (int r = 0; r < 4; r++) {
            m12[r] = active ? s12[r] : -1e30f;
            m3[r]  = active ? s3[r]  : -1e30f;
        }
        #pragma unroll
        for (int off = 16; off > 0; off >>= 1) {
            #pragma unroll
            for (int r = 0; r < 4; r++) {
                m12[r] = fmaxf(m12[r], __shfl_xor_sync(0xffffffffu, m12[r], off));
                m3[r]  = fmaxf(m3[r],  __shfl_xor_sync(0xffffffffu, m3[r],  off));
            }
        }
        if (lane == 0) {
            #pragma unroll
            for (int r = 0; r < 4; r++) { red[wid][r] = m12[r]; red[wid][4 + r] = m3[r]; }
        }
        __syncthreads();
        #pragma unroll
        for (int ww = 0; ww < 7; ww++)
            #pragma unroll
            for (int r = 0; r < 4; r++) {
                m12[r] = fmaxf(m12[r], red[ww][r]);
                m3[r]  = fmaxf(m3[r],  red[ww][4 + r]);
            }

        // ---- exps + block sum reduce (12 values) ----
        float e1[4], e2[4], e3[4], z1[4], z2[4], z3[4];
        #pragma unroll
        for (int r = 0; r < 4; r++) {
            float d12 = s12[r] - m12[r];
            e1[r] = active ? __expf(d12)            : 0.f;
            e2[r] = active ? __expf(d12 * 0.125f)   : 0.f;   // 1/sqrt(64)
            e3[r] = active ? __expf(s3[r] - m3[r])  : 0.f;
            z1[r] = e1[r]; z2[r] = e2[r]; z3[r] = e3[r];
        }
        #pragma unroll
        for (int off = 16; off > 0; off >>= 1) {
            #pragma unroll
            for (int r = 0; r < 4; r++) {
                z1[r] += __shfl_xor_sync(0xffffffffu, z1[r], off);
                z2[r] += __shfl_xor_sync(0xffffffffu, z2[r], off);
                z3[r] += __shfl_xor_sync(0xffffffffu, z3[r], off);
            }
        }
        if (lane == 0) {
            #pragma unroll
            for (int r = 0; r < 4; r++) {
                red[wid][8 + r] = z1[r]; red[wid][12 + r] = z2[r]; red[wid][16 + r] = z3[r];
            }
        }
        __syncthreads();
        #pragma unroll
        for (int r = 0; r < 4; r++) {
            float t1 = 0.f, t2 = 0.f, t3 = 0.f;
            #pragma unroll
            for (int ww = 0; ww < 7; ww++) {
                t1 += red[ww][8 + r]; t2 += red[ww][12 + r]; t3 += red[ww][16 + r];
            }
            if (active && (i0 + r) < row_end) {
                float p = (e1[r] * rcp_approx(t1)
                         + e2[r] * rcp_approx(t2)
                         + e3[r] * rcp_approx(t3)) * (1.0f / 3.0f);
                Prow[(i0 + r) * 197 + tid] = p;
            }
        }
    }
}

// ---------------------------------------------------------------------------
// K3: ctx = P @ V, scattered to (b, n, h*64+hd). grid (7 row-tiles, 48 heads).
// Warp handles 4 output rows; lanes cover hd 0..63 (two accumulator halves).
// ---------------------------------------------------------------------------
__global__ void __launch_bounds__(256) pv_kernel(float* __restrict__ outp)
{
    extern __shared__ float sm3[];
    float* Ps = sm3;              // [32][197]
    float* Vs = sm3 + 32 * 197;   // [197][64]
    const int tile = blockIdx.x, head = blockIdx.y;
    const int i_base = tile * 32;
    const int tid = threadIdx.x;

    const float* Pg = g_P + head * (197 * 197);
    const float* vg = g_v + head * (197 * 64);
    for (int idx = tid; idx < 32 * 197; idx += 256) {
        int gi = i_base + idx / 197;
        Ps[idx] = (gi < 197) ? Pg[i_base * 197 + idx] : 0.f;
    }
    for (int idx = tid; idx < 197 * 64; idx += 256) Vs[idx] = vg[idx];
    __syncthreads();

    const int warp = tid >> 5, lane = tid & 31;
    float acc0[4] = {0,0,0,0}, acc1[4] = {0,0,0,0};
    #pragma unroll 4
    for (int j = 0; j < 197; j++) {
        float v0 = Vs[j * 64 + lane];
        float v1 = Vs[j * 64 + 32 + lane];
        #pragma unroll
        for (int r = 0; r < 4; r++) {
            float p = Ps[(warp * 4 + r) * 197 + j];   // broadcast
            acc0[r] = fmaf(p, v0, acc0[r]);
            acc1[r] = fmaf(p, v1, acc1[r]);
        }
    }
    const int b = head / 12, h = head % 12;
    #pragma unroll
    for (int r = 0; r < 4; r++) {
        int i = i_base + warp * 4 + r;
        if (i < 197) {
            float* dst = outp + (b * 197 + i) * 768 + h * 64;
            dst[lane]      = acc0[r];
            dst[32 + lane] = acc1[r];
        }
    }
}

// ---------------------------------------------------------------------------
extern "C" void kernel_launch(void* const* d_in, const int* in_sizes, int n_in,
                              void* d_out, int out_size)
{
    const float* hid = (const float*)d_in[0];
    const float* Wq  = (const float*)d_in[1];
    const float* bq  = (const float*)d_in[2];
    const float* Wk  = (const float*)d_in[3];
    const float* bk  = (const float*)d_in[4];
    const float* Wv  = (const float*)d_in[5];
    const float* bv  = (const float*)d_in[6];
    const float* Ws  = (const float*)d_in[7];
    // d_in[8] (bs) is row-constant in a softmax -> mathematically a no-op.
    float* out = (float*)d_out;

    const int smem_k2 = 197 * 64 * 2 * 4 + 64 * 4;            // 101120 B
    const int smem_k3 = (32 * 197 + 197 * 64) * 4;            //  75648 B
    cudaFuncSetAttribute(attn_probs_kernel, cudaFuncAttributeMaxDynamicSharedMemorySize, smem_k2);
    cudaFuncSetAttribute(pv_kernel,         cudaFuncAttributeMaxDynamicSharedMemorySize, smem_k3);

    qkv_gemm<<<dim3(13, 36), 256>>>(hid, Wq, bq, Wk, bk, Wv, bv);
    attn_probs_kernel<<<dim3(3, 48), 224, smem_k2>>>(Ws);
    pv_kernel<<<dim3(7, 48), 256, smem_k3>>>(out);
}

// round 3
// speedup vs baseline: 1.0706x; 1.0706x over previous
#include <cuda_runtime.h>
#include <math.h>

#define BB 4
#define NN 197
#define DD 768
#define HH 12
#define HDIM 64
#define NHEAD (BB*HH)   /* 48 */

typedef unsigned long long ULL;

// Scratch (no allocations allowed): ~22 MB total
__device__ float g_q[NHEAD*NN*HDIM];
__device__ float g_k[NHEAD*NN*HDIM];
__device__ float g_v[NHEAD*NN*HDIM];
__device__ float g_P[NHEAD*NN*NN];

// ---- packed fp32x2 helpers (Blackwell sm_100a+) ------------------------------
__device__ __forceinline__ ULL pk2(float x) {
    ULL r; asm("mov.b64 %0, {%1, %1};" : "=l"(r) : "f"(x)); return r;
}
__device__ __forceinline__ void fma2(ULL& d, ULL a, ULL b) {
    asm("fma.rn.f32x2 %0, %1, %2, %0;" : "+l"(d) : "l"(a), "l"(b));
}
__device__ __forceinline__ float2 up2(ULL v) {
    float2 r; asm("mov.b64 {%0, %1}, %2;" : "=f"(r.x), "=f"(r.y) : "l"(v)); return r;
}

// ---------------------------------------------------------------------------
// K1: QKV projection with f32x2 FMA. C = hidden(788x768) @ W(768x768) + bias,
// scattered into per-head layout g_{q,k,v}[(b*12+h)*197 + n][hd].
// 128x128x16 tiles, double-buffered smem, 8x8 microtile as 4 rowpair x 8 col
// f32x2 accumulators. grid (7, 18): blockIdx.y = proj*6 + coltile.
// ---------------------------------------------------------------------------
__global__ void __launch_bounds__(256) qkv_gemm(
    const float* __restrict__ hid,
    const float* __restrict__ Wq, const float* __restrict__ bq,
    const float* __restrict__ Wk, const float* __restrict__ bk,
    const float* __restrict__ Wv, const float* __restrict__ bv)
{
    __shared__ float As[2][16][128];   // [buf][k][m]
    __shared__ float Bs[2][16][128];   // [buf][k][n]

    const int tid   = threadIdx.x;
    const int m0    = blockIdx.x * 128;
    const int nt    = blockIdx.y;          // 0..17
    const int proj  = nt / 6;
    const int ncol0 = (nt % 6) * 128;      // column offset within W

    const float* W; const float* bias; float* outp;
    if (proj == 0)      { W = Wq; bias = bq; outp = g_q; }
    else if (proj == 1) { W = Wk; bias = bk; outp = g_k; }
    else                { W = Wv; bias = bv; outp = g_v; }

    const int ty = tid >> 4, tx = tid & 15;     // 16x16 compute map

    // A loader: quad qq -> m_l = qq>>2, k-quad = (qq&3)*4; this thread: qq=tid, tid+256
    const int am  = tid >> 2;                   // 0..63
    const int ak0 = (tid & 3) * 4;              // 0,4,8,12
    // B loader: qq=tid -> kk = tid>>5 (0..7), n = (tid&31)*4; second: kk+8
    const int bkl = tid >> 5;
    const int bn4 = (tid & 31) * 4;

    ULL acc[4][8];
    #pragma unroll
    for (int r = 0; r < 4; r++)
        #pragma unroll
        for (int j = 0; j < 8; j++) acc[r][j] = 0ull;

    const int gm0 = m0 + am, gm1 = m0 + 64 + am;
    const float4 f4z = make_float4(0.f, 0.f, 0.f, 0.f);

    float4 aR0, aR1, bR0, bR1;
    // prologue load (k0 = 0)
    aR0 = (gm0 < 788) ? *(const float4*)(hid + gm0 * 768 + ak0) : f4z;
    aR1 = (gm1 < 788) ? *(const float4*)(hid + gm1 * 768 + ak0) : f4z;
    bR0 = *(const float4*)(W + (bkl    ) * 768 + ncol0 + bn4);
    bR1 = *(const float4*)(W + (bkl + 8) * 768 + ncol0 + bn4);
    {
        As[0][ak0+0][am] = aR0.x; As[0][ak0+1][am] = aR0.y;
        As[0][ak0+2][am] = aR0.z; As[0][ak0+3][am] = aR0.w;
        As[0][ak0+0][64+am] = aR1.x; As[0][ak0+1][64+am] = aR1.y;
        As[0][ak0+2][64+am] = aR1.z; As[0][ak0+3][64+am] = aR1.w;
        *(float4*)&Bs[0][bkl    ][bn4] = bR0;
        *(float4*)&Bs[0][bkl + 8][bn4] = bR1;
    }
    __syncthreads();

    int buf = 0;
    for (int kt = 0; kt < 48; kt++) {
        if (kt < 47) {
            const int k0 = (kt + 1) * 16;
            aR0 = (gm0 < 788) ? *(const float4*)(hid + gm0 * 768 + k0 + ak0) : f4z;
            aR1 = (gm1 < 788) ? *(const float4*)(hid + gm1 * 768 + k0 + ak0) : f4z;
            bR0 = *(const float4*)(W + (k0 + bkl    ) * 768 + ncol0 + bn4);
            bR1 = *(const float4*)(W + (k0 + bkl + 8) * 768 + ncol0 + bn4);
        }

        #pragma unroll
        for (int kk = 0; kk < 16; kk++) {
            const ULL* ap = (const ULL*)&As[buf][kk][ty * 8];   // 4 row pairs
            ULL a0 = ap[0], a1 = ap[1], a2 = ap[2], a3 = ap[3];
            float4 b0 = *(float4*)&Bs[buf][kk][tx * 8];
            float4 b1 = *(float4*)&Bs[buf][kk][tx * 8 + 4];
            ULL bd[8];
            bd[0] = pk2(b0.x); bd[1] = pk2(b0.y); bd[2] = pk2(b0.z); bd[3] = pk2(b0.w);
            bd[4] = pk2(b1.x); bd[5] = pk2(b1.y); bd[6] = pk2(b1.z); bd[7] = pk2(b1.w);
            #pragma unroll
            for (int j = 0; j < 8; j++) {
                fma2(acc[0][j], a0, bd[j]);
                fma2(acc[1][j], a1, bd[j]);
                fma2(acc[2][j], a2, bd[j]);
                fma2(acc[3][j], a3, bd[j]);
            }
        }

        if (kt < 47) {
            const int nb = buf ^ 1;
            As[nb][ak0+0][am] = aR0.x; As[nb][ak0+1][am] = aR0.y;
            As[nb][ak0+2][am] = aR0.z; As[nb][ak0+3][am] = aR0.w;
            As[nb][ak0+0][64+am] = aR1.x; As[nb][ak0+1][64+am] = aR1.y;
            As[nb][ak0+2][64+am] = aR1.z; As[nb][ak0+3][64+am] = aR1.w;
            *(float4*)&Bs[nb][bkl    ][bn4] = bR0;
            *(float4*)&Bs[nb][bkl + 8][bn4] = bR1;
            __syncthreads();
            buf = nb;
        }
    }

    // epilogue: add bias, scatter to per-head layout
    #pragma unroll
    for (int j = 0; j < 8; j++) {
        const int nc = ncol0 + tx * 8 + j;     // column within this projection
        const int h  = nc >> 6, hd = nc & 63;
        const float bb = __ldg(bias + nc);
        #pragma unroll
        for (int r = 0; r < 4; r++) {
            float2 v = up2(acc[r][j]);
            int ma = m0 + ty * 8 + 2 * r;
            if (ma < 788) {
                int b = ma / 197, n = ma - b * 197;
                outp[((b * 12 + h) * 197 + n) * 64 + hd] = v.x + bb;
            }
            int mb = ma + 1;
            if (mb < 788) {
                int b = mb / 197, n = mb - b * 197;
                outp[((b * 12 + h) * 197 + n) * 64 + hd] = v.y + bb;
            }
        }
    }
}

// ---------------------------------------------------------------------------
// K2: fused logits + 3-way softmax -> combined probability matrix P.
// (unchanged — MUFU/tanh bound; f32x2 doesn't apply)
// ---------------------------------------------------------------------------
__device__ __forceinline__ float tanh_approx(float x) {
    float y; asm("tanh.approx.f32 %0, %1;" : "=f"(y) : "f"(x)); return y;
}
__device__ __forceinline__ float rcp_approx(float x) {
    float y; asm("rcp.approx.f32 %0, %1;" : "=f"(y) : "f"(x)); return y;
}

__global__ void __launch_bounds__(224) attn_probs_kernel(const float* __restrict__ Wsp)
{
    extern __shared__ float sm[];
    float2* qk  = (float2*)sm;            // [197][64]  (q, k) interleaved
    float*  wss = sm + 197 * 64 * 2;      // [64]
    __shared__ float red[7][20];

    const int head      = blockIdx.y;
    const int chunk     = blockIdx.x;
    const int row_begin = chunk * 66;
    const int row_end   = min(197, row_begin + 66);
    const int tid  = threadIdx.x;
    const int wid  = tid >> 5, lane = tid & 31;

    const float* qg = g_q + head * (197 * 64);
    const float* kg = g_k + head * (197 * 64);
    for (int idx = tid; idx < 197 * 64; idx += 224)
        qk[idx] = make_float2(qg[idx], kg[idx]);
    if (tid < 64) wss[tid] = Wsp[tid];
    __syncthreads();

    const bool active = (tid < 197);
    const int jj = active ? tid : 0;
    float qj[64], kj[64];
    #pragma unroll
    for (int d = 0; d < 64; d++) { float2 t = qk[jj * 64 + d]; qj[d] = t.x; kj[d] = t.y; }

    float* Prow = g_P + head * (197 * 197);

    for (int i0 = row_begin; i0 < row_end; i0 += 4) {
        const float2* qp[4];
        #pragma unroll
        for (int r = 0; r < 4; r++) qp[r] = qk + min(i0 + r, 196) * 64;

        float s12[4] = {0,0,0,0}, s3[4] = {0,0,0,0};
        #pragma unroll
        for (int d = 0; d < 64; d++) {
            float wsd = wss[d];
            float2 av[4];
            #pragma unroll
            for (int r = 0; r < 4; r++) av[r] = qp[r][d];   // broadcast LDS.64
            #pragma unroll
            for (int r = 0; r < 4; r++) {
                s12[r] = fmaf(av[r].x, kj[d], s12[r]);                  // q_i . k_j
                s3[r]  = fmaf(wsd, tanh_approx(av[r].y + qj[d]), s3[r]); // Ws.tanh(k_i+q_j)
            }
        }

        // ---- block max reduce ----
        float m12[4], m3[4];
        #pragma unroll
        for (int r = 0; r < 4; r++) {
            m12[r] = active ? s12[r] : -1e30f;
            m3[r]  = active ? s3[r]  : -1e30f;
        }
        #pragma unroll
        for (int off = 16; off > 0; off >>= 1) {
            #pragma unroll
            for (int r = 0; r < 4; r++) {
                m12[r] = fmaxf(m12[r], __shfl_xor_sync(0xffffffffu, m12[r], off));
                m3[r]  = fmaxf(m3[r],  __shfl_xor_sync(0xffffffffu, m3[r],  off));
            }
        }
        if (lane == 0) {
            #pragma unroll
            for (int r = 0; r < 4; r++) { red[wid][r] = m12[r]; red[wid][4 + r] = m3[r]; }
        }
        __syncthreads();
        #pragma unroll
        for (int ww = 0; ww < 7; ww++)
            #pragma unroll
            for (int r = 0; r < 4; r++) {
                m12[r] = fmaxf(m12[r], red[ww][r]);
                m3[r]  = fmaxf(m3[r],  red[ww][4 + r]);
            }

        // ---- exps + block sum reduce ----
        float e1[4], e2[4], e3[4], z1[4], z2[4], z3[4];
        #pragma unroll
        for (int r = 0; r < 4; r++) {
            float d12 = s12[r] - m12[r];
            e1[r] = active ? __expf(d12)            : 0.f;
            e2[r] = active ? __expf(d12 * 0.125f)   : 0.f;   // 1/sqrt(64)
            e3[r] = active ? __expf(s3[r] - m3[r])  : 0.f;
            z1[r] = e1[r]; z2[r] = e2[r]; z3[r] = e3[r];
        }
        #pragma unroll
        for (int off = 16; off > 0; off >>= 1) {
            #pragma unroll
            for (int r = 0; r < 4; r++) {
                z1[r] += __shfl_xor_sync(0xffffffffu, z1[r], off);
                z2[r] += __shfl_xor_sync(0xffffffffu, z2[r], off);
                z3[r] += __shfl_xor_sync(0xffffffffu, z3[r], off);
            }
        }
        if (lane == 0) {
            #pragma unroll
            for (int r = 0; r < 4; r++) {
                red[wid][8 + r] = z1[r]; red[wid][12 + r] = z2[r]; red[wid][16 + r] = z3[r];
            }
        }
        __syncthreads();
        #pragma unroll
        for (int r = 0; r < 4; r++) {
            float t1 = 0.f, t2 = 0.f, t3 = 0.f;
            #pragma unroll
            for (int ww = 0; ww < 7; ww++) {
                t1 += red[ww][8 + r]; t2 += red[ww][12 + r]; t3 += red[ww][16 + r];
            }
            if (active && (i0 + r) < row_end) {
                float p = (e1[r] * rcp_approx(t1)
                         + e2[r] * rcp_approx(t2)
                         + e3[r] * rcp_approx(t3)) * (1.0f / 3.0f);
                Prow[(i0 + r) * 197 + tid] = p;
            }
        }
    }
}

// ---------------------------------------------------------------------------
// K3: ctx = P @ V with f32x2. Warp handles 4 output rows; lanes own hd pairs
// (hd = 2*lane, 2*lane+1). grid (7 row-tiles, 48 heads).
// ---------------------------------------------------------------------------
__global__ void __launch_bounds__(256) pv_kernel(float* __restrict__ outp)
{
    extern __shared__ float sm3[];
    float* Ps = sm3;              // [32][197]
    float* Vs = sm3 + 32 * 197;   // [197][64]
    const int tile = blockIdx.x, head = blockIdx.y;
    const int i_base = tile * 32;
    const int tid = threadIdx.x;

    const float* Pg = g_P + head * (197 * 197);
    const float* vg = g_v + head * (197 * 64);
    for (int idx = tid; idx < 32 * 197; idx += 256) {
        int gi = i_base + idx / 197;
        Ps[idx] = (gi < 197) ? Pg[i_base * 197 + idx] : 0.f;
    }
    for (int idx = tid; idx < 197 * 64; idx += 256) Vs[idx] = vg[idx];
    __syncthreads();

    const int warp = tid >> 5, lane = tid & 31;
    ULL acc[4] = {0ull, 0ull, 0ull, 0ull};
    #pragma unroll 4
    for (int j = 0; j < 197; j++) {
        ULL vj = *(const ULL*)&Vs[j * 64 + 2 * lane];     // hd pair
        #pragma unroll
        for (int r = 0; r < 4; r++) {
            ULL pd = pk2(Ps[(warp * 4 + r) * 197 + j]);   // broadcast
            fma2(acc[r], pd, vj);
        }
    }
    const int b = head / 12, h = head % 12;
    #pragma unroll
    for (int r = 0; r < 4; r++) {
        int i = i_base + warp * 4 + r;
        if (i < 197) {
            float* dst = outp + (b * 197 + i) * 768 + h * 64;
            *(float2*)(dst + 2 * lane) = up2(acc[r]);
        }
    }
}

// ---------------------------------------------------------------------------
extern "C" void kernel_launch(void* const* d_in, const int* in_sizes, int n_in,
                              void* d_out, int out_size)
{
    const float* hid = (const float*)d_in[0];
    const float* Wq  = (const float*)d_in[1];
    const float* bq  = (const float*)d_in[2];
    const float* Wk  = (const float*)d_in[3];
    const float* bk  = (const float*)d_in[4];
    const float* Wv  = (const float*)d_in[5];
    const float* bv  = (const float*)d_in[6];
    const float* Ws  = (const float*)d_in[7];
    // d_in[8] (bs) is row-constant in a softmax -> mathematically a no-op.
    float* out = (float*)d_out;

    const int smem_k2 = 197 * 64 * 2 * 4 + 64 * 4;            // 101120 B
    const int smem_k3 = (32 * 197 + 197 * 64) * 4;            //  75648 B
    cudaFuncSetAttribute(attn_probs_kernel, cudaFuncAttributeMaxDynamicSharedMemorySize, smem_k2);
    cudaFuncSetAttribute(pv_kernel,         cudaFuncAttributeMaxDynamicSharedMemorySize, smem_k3);

    qkv_gemm<<<dim3(7, 18), 256>>>(hid, Wq, bq, Wk, bk, Wv, bv);
    attn_probs_kernel<<<dim3(3, 48), 224, smem_k2>>>(Ws);
    pv_kernel<<<dim3(7, 48), 256, smem_k3>>>(out);
}